// round 3
// baseline (speedup 1.0000x reference)
#include <cuda_runtime.h>
#include <math.h>

#define BS 128
#define LATENT 512
#define HID 1024
#define G4 4096   // 4*HID
#define NBLK 128
#define NTHR 256

typedef unsigned long long u64;

// Persistent device-global state (allocation-free scratch).
__device__ float g_Wx[2][G4][LATENT];   // gate-interleaved Wih per dir
__device__ float g_Wh[2][G4][HID];      // gate-interleaved Whh per dir
__device__ float g_bias[2][G4];         // gate-interleaved bias per dir
__device__ float g_x[BS][LATENT];       // current decoder input
__device__ float g_h[2][2][BS][HID];    // [buf][dir][b][j] (double-buffered)
__device__ float g_c[2][BS][HID];       // [dir][b][j]
__device__ u64   g_arrive;              // grid-barrier arrival counter

__device__ __forceinline__ u64 pack2(float lo, float hi) {
    u64 r; asm("mov.b64 %0, {%1, %2};" : "=l"(r) : "f"(lo), "f"(hi)); return r;
}
__device__ __forceinline__ void unpack2(u64 v, float& lo, float& hi) {
    asm("mov.b64 {%0, %1}, %2;" : "=f"(lo), "=f"(hi) : "l"(v));
}
__device__ __forceinline__ void fma2(u64& d, u64 a, u64 b) {
    asm("fma.rn.f32x2 %0, %1, %2, %0;" : "+l"(d) : "l"(a), "l"(b));
}

// Grid-wide barrier: monotonically increasing arrival counter (reset in prep).
// Leading threadfence = release (flush writes); trailing threadfence (gpu
// scope -> CCTL.IVALL) = acquire (invalidate stale L1 lines).
__device__ __forceinline__ void grid_sync(u64 target) {
    __threadfence();
    __syncthreads();
    if (threadIdx.x == 0) {
        atomicAdd(&g_arrive, 1ULL);
        u64 v;
        do { v = *(volatile u64*)&g_arrive; } while (v < target);
    }
    __syncthreads();
    __threadfence();
}

// ---------------------------------------------------------------------------
// Prep: gate-interleave weights (reordered row r -> orig row (r&3)*HID + (r>>2))
// so each 4-column group is a complete (i,f,g,o) quadruple. Init x, h, c, bar.
// ---------------------------------------------------------------------------
__global__ void prep_kernel(const float* __restrict__ Wih_f, const float* __restrict__ Whh_f,
                            const float* __restrict__ b_f,
                            const float* __restrict__ Wih_b, const float* __restrict__ Whh_b,
                            const float* __restrict__ b_b,
                            const float* __restrict__ dec) {
    int idx = blockIdx.x * blockDim.x + threadIdx.x;
    int stride = gridDim.x * blockDim.x;
    if (idx == 0) g_arrive = 0ULL;
    for (int i = idx; i < 2 * G4 * LATENT; i += stride) {
        int dir = i / (G4 * LATENT);
        int rem = i - dir * (G4 * LATENT);
        int r = rem / LATENT, k = rem - r * LATENT;
        int orow = (r & 3) * HID + (r >> 2);
        const float* W = dir ? Wih_b : Wih_f;
        g_Wx[dir][r][k] = W[orow * LATENT + k];
    }
    for (int i = idx; i < 2 * G4 * HID; i += stride) {
        int dir = i / (G4 * HID);
        int rem = i - dir * (G4 * HID);
        int r = rem / HID, k = rem - r * HID;
        int orow = (r & 3) * HID + (r >> 2);
        const float* W = dir ? Whh_b : Whh_f;
        g_Wh[dir][r][k] = W[orow * HID + k];
    }
    for (int i = idx; i < 2 * G4; i += stride) {
        int dir = i / G4, r = i - dir * G4;
        g_bias[dir][r] = (dir ? b_b : b_f)[(r & 3) * HID + (r >> 2)];
    }
    for (int i = idx; i < BS * LATENT; i += stride) ((float*)g_x)[i] = dec[i];
    for (int i = idx; i < 2 * BS * HID; i += stride) {
        ((float*)g_h[0])[i] = 0.f;
        ((float*)g_h[1])[i] = 0.f;
        ((float*)g_c)[i]    = 0.f;
    }
}

// ---------------------------------------------------------------------------
// Persistent kernel: all T steps in one launch. 128 blocks x 256 threads.
// Per step:
//   phase A (GEMM+cell): block = (dir, 64-col tile); M=128, N=64, K=1536.
//   grid_sync
//   phase B (head): block = (btile of 8 rows, ltile of 64 cols) for x_next;
//                   ltile==0 blocks also compute the fc1 output scalar.
//   grid_sync
// ---------------------------------------------------------------------------
__global__ void __launch_bounds__(NTHR, 1) lstm_persist(
        int T, float* __restrict__ out,
        const float* __restrict__ W_out, const float* __restrict__ b_out,
        const float* __restrict__ W_fc1, const float* __restrict__ b_fc1) {

    __shared__ __align__(16) unsigned char sraw[33 * 1024];
    u64   (*As2)[128]  = (u64 (*)[128])sraw;                 // 16 KB, dup-packed A
    float (*Bsf)[64]   = (float (*)[64])(sraw + 16384);      // 4 KB
    float (*s_hb)[HID] = (float (*)[HID])sraw;               // 32 KB (head phase)

    const int tid = threadIdx.x;
    const int bid = blockIdx.x;

    // GEMM-phase mapping
    const int dir = bid >> 6;
    const int colbase = (bid & 63) << 6;
    const int ty = tid >> 3;            // 0..31 -> rows ty*4..+3
    const int tx = tid & 7;             // 0..7  -> cols tx*8..+7
    const int ty4 = ty * 4;

    // Head-phase mapping
    const int bt = bid >> 3;            // 0..15 -> rows bt*8..+7
    const int lt = bid & 7;             // 0..7  -> latent cols lt*64..+63

    u64 nbar = 0;

    for (int t = 0; t < T; t++) {
        const int cur = t & 1;
        const int nxt = cur ^ 1;

        // ================= phase A: z-GEMM + LSTM cell =================
        u64 acc[4][4];
#pragma unroll
        for (int i = 0; i < 4; i++)
#pragma unroll
            for (int j = 0; j < 4; j++) acc[i][j] = 0ull;

#pragma unroll 1
        for (int phase = 0; phase < 2; phase++) {
            const int K = phase ? HID : LATENT;
            const float* __restrict__ A = phase ? &g_h[cur][dir][0][0] : &g_x[0][0];
            const float* __restrict__ W = phase ? &g_Wh[dir][colbase][0]
                                                : &g_Wx[dir][colbase][0];
#pragma unroll 1
            for (int k0 = 0; k0 < K; k0 += 16) {
                // stage A: 128 rows x 16 k, duplicated pairs
                {
                    int row = tid & 127;
                    int kh  = (tid >> 7) * 8;
                    const float4* ap = (const float4*)(A + row * K + k0 + kh);
                    float4 v0 = ap[0], v1 = ap[1];
                    As2[kh + 0][row] = pack2(v0.x, v0.x);
                    As2[kh + 1][row] = pack2(v0.y, v0.y);
                    As2[kh + 2][row] = pack2(v0.z, v0.z);
                    As2[kh + 3][row] = pack2(v0.w, v0.w);
                    As2[kh + 4][row] = pack2(v1.x, v1.x);
                    As2[kh + 5][row] = pack2(v1.y, v1.y);
                    As2[kh + 6][row] = pack2(v1.z, v1.z);
                    As2[kh + 7][row] = pack2(v1.w, v1.w);
                }
                // stage B: 64 cols x 16 k
                {
                    int col = tid >> 2;
                    int kq  = (tid & 3) * 4;
                    const float4* wp = (const float4*)(W + col * K + k0 + kq);
                    float4 w = wp[0];
                    Bsf[kq + 0][col] = w.x;
                    Bsf[kq + 1][col] = w.y;
                    Bsf[kq + 2][col] = w.z;
                    Bsf[kq + 3][col] = w.w;
                }
                __syncthreads();

#pragma unroll
                for (int kk = 0; kk < 16; kk++) {
                    ulonglong2 a01 = *(const ulonglong2*)&As2[kk][ty4];
                    ulonglong2 a23 = *(const ulonglong2*)&As2[kk][ty4 + 2];
                    const ulonglong2* bp = (const ulonglong2*)&Bsf[kk][tx * 8];
                    ulonglong2 b01 = bp[0], b23 = bp[1];
                    fma2(acc[0][0], a01.x, b01.x); fma2(acc[0][1], a01.x, b01.y);
                    fma2(acc[0][2], a01.x, b23.x); fma2(acc[0][3], a01.x, b23.y);
                    fma2(acc[1][0], a01.y, b01.x); fma2(acc[1][1], a01.y, b01.y);
                    fma2(acc[1][2], a01.y, b23.x); fma2(acc[1][3], a01.y, b23.y);
                    fma2(acc[2][0], a23.x, b01.x); fma2(acc[2][1], a23.x, b01.y);
                    fma2(acc[2][2], a23.x, b23.x); fma2(acc[2][3], a23.x, b23.y);
                    fma2(acc[3][0], a23.y, b01.x); fma2(acc[3][1], a23.y, b01.y);
                    fma2(acc[3][2], a23.y, b23.x); fma2(acc[3][3], a23.y, b23.y);
                }
                __syncthreads();
            }
        }

        // cell epilogue: 2 (i,f,g,o) quadruples x 4 rows per thread
#pragma unroll
        for (int grp = 0; grp < 2; grp++) {
            const int cb = colbase + tx * 8 + grp * 4;
            const int jprime = cb >> 2;
            const float bi = g_bias[dir][cb + 0];
            const float bf = g_bias[dir][cb + 1];
            const float bg = g_bias[dir][cb + 2];
            const float bo = g_bias[dir][cb + 3];
#pragma unroll
            for (int i = 0; i < 4; i++) {
                const int row = ty4 + i;
                float zi, zf, zg, zo;
                unpack2(acc[i][grp * 2 + 0], zi, zf);
                unpack2(acc[i][grp * 2 + 1], zg, zo);
                zi += bi; zf += bf; zg += bg; zo += bo;
                float si = 1.f / (1.f + expf(-zi));
                float sf = 1.f / (1.f + expf(-zf));
                float so = 1.f / (1.f + expf(-zo));
                float c2 = sf * g_c[dir][row][jprime] + si * tanhf(zg);
                g_c[dir][row][jprime] = c2;
                g_h[nxt][dir][row][jprime] = so * tanhf(c2);
            }
        }

        nbar++; grid_sync(nbar * NBLK);

        // ================= phase B: head =================
        // stage hb rows bt*8..+7 into smem
        for (int i = tid; i < 8 * HID / 4; i += NTHR) {
            int r = (i * 4) >> 10;
            int k = (i * 4) & (HID - 1);
            *(float4*)&s_hb[r][k] = *(const float4*)&g_h[nxt][1][bt * 8 + r][k];
        }
        __syncthreads();

        // x_next = hb @ W_out^T + b_out  (this block: 8 b-rows x 64 l-cols)
        {
            const int l_loc = tid >> 2;
            const int q = tid & 3;
            const int l = lt * 64 + l_loc;
            const u64* __restrict__ wp = (const u64*)(W_out + (size_t)l * HID + q * 256);
            const u64* __restrict__ hp = (const u64*)&s_hb[0][q * 256];
            u64 hacc[8];
#pragma unroll
            for (int r = 0; r < 8; r++) hacc[r] = 0ull;
#pragma unroll 2
            for (int k2 = 0; k2 < 128; k2++) {
                u64 w = wp[k2];
#pragma unroll
                for (int r = 0; r < 8; r++) fma2(hacc[r], w, hp[r * 512 + k2]);
            }
#pragma unroll
            for (int r = 0; r < 8; r++) {
                float lo, hi; unpack2(hacc[r], lo, hi);
                float s = lo + hi;
                s += __shfl_xor_sync(0xffffffffu, s, 1);
                s += __shfl_xor_sync(0xffffffffu, s, 2);
                if (q == 0) g_x[bt * 8 + r][l] = s + b_out[l];
            }
        }

        // out[b, t] = relu(concat(hf,hb)) . W_fc1 + b_fc1  (ltile 0 blocks)
        if (lt == 0) {
            const int r = tid >> 5, lane = tid & 31;
            const int b = bt * 8 + r;
            const float* __restrict__ hf = &g_h[nxt][0][b][0];
            float facc = 0.f;
            for (int k = lane * 4; k < HID; k += 128) {
                float4 f  = *(const float4*)&hf[k];
                float4 wf = *(const float4*)&W_fc1[k];
                float4 hb4 = *(const float4*)&s_hb[r][k];
                float4 wb = *(const float4*)&W_fc1[HID + k];
                facc += fmaxf(f.x, 0.f) * wf.x + fmaxf(f.y, 0.f) * wf.y
                      + fmaxf(f.z, 0.f) * wf.z + fmaxf(f.w, 0.f) * wf.w
                      + fmaxf(hb4.x, 0.f) * wb.x + fmaxf(hb4.y, 0.f) * wb.y
                      + fmaxf(hb4.z, 0.f) * wb.z + fmaxf(hb4.w, 0.f) * wb.w;
            }
#pragma unroll
            for (int off = 16; off; off >>= 1)
                facc += __shfl_xor_sync(0xffffffffu, facc, off);
            if (lane == 0) out[(size_t)b * T + t] = facc + b_fc1[0];
        }

        nbar++; grid_sync(nbar * NBLK);
    }
}

// ---------------------------------------------------------------------------
extern "C" void kernel_launch(void* const* d_in, const int* in_sizes, int n_in,
                              void* d_out, int out_size) {
    const float* dec   = (const float*)d_in[0];
    // d_in[1] = lengths (T derives from out_size)
    const float* Wih_f = (const float*)d_in[2];
    const float* Whh_f = (const float*)d_in[3];
    const float* b_f   = (const float*)d_in[4];
    const float* Wih_b = (const float*)d_in[5];
    const float* Whh_b = (const float*)d_in[6];
    const float* b_b   = (const float*)d_in[7];
    const float* W_out = (const float*)d_in[8];
    const float* b_out = (const float*)d_in[9];
    const float* W_fc1 = (const float*)d_in[10];
    const float* b_fc1 = (const float*)d_in[11];
    float* out = (float*)d_out;

    const int T = out_size / BS;

    prep_kernel<<<1024, 256>>>(Wih_f, Whh_f, b_f, Wih_b, Whh_b, b_b, dec);
    if (T > 0) {
        lstm_persist<<<NBLK, NTHR>>>(T, out, W_out, b_out, W_fc1, b_fc1);
    }
}